// round 4
// baseline (speedup 1.0000x reference)
#include <cuda_runtime.h>

// SpinorBilinears: psi [B=8, N=65536, S=4] f32, gamma [C=8, 4, 4] f32.
// Outputs flat in d_out: K0 [BN] | K1 [BN,8,8] | K2 [BN,8,8]
//   u_c = gamma_c^T p,  v_c = gamma_c p,  W[c][d] = u_c . v_d
//   K1 = 0.5 (W - W^T),  K2 = 0.5 (W + W^T)
//
// Cooperative layout: 8 threads per token (c = tid&7). Each thread computes
// u_c, v_c, shares them via padded smem, then computes and stores row c of
// K1/K2 directly (contiguous 32 B per thread -> fully coalesced warp stores).

#define TPB 256
#define TOKS 32            // tokens per block = TPB/8

__device__ __forceinline__ float dot4f(float4 a, float4 b) {
    return fmaf(a.x, b.x, fmaf(a.y, b.y, fmaf(a.z, b.z, a.w * b.w)));
}

__global__ __launch_bounds__(TPB) void spinor_bilinears_kernel(
    const float4* __restrict__ psi4,
    const float4* __restrict__ gamma4,
    float* __restrict__ out,
    int BN)
{
    __shared__ float4 sg[32];             // gamma: 8 matrices x 4 rows
    __shared__ float4 su[TOKS * 9];       // u vectors, padded stride 9 (conflict-free)
    __shared__ float4 sv[TOKS * 9];       // v vectors

    const int tid  = threadIdx.x;
    const int tokL = tid >> 3;            // local token 0..31
    const int c    = tid & 7;             // coordinate index 0..7

    if (tid < 32) sg[tid] = gamma4[tid];
    __syncthreads();

    const int t = blockIdx.x * TOKS + tokL;     // global token (grid exact)

    // ---- spinor load (4 distinct 16B per warp, sector-coalesced) ----
    const float4 p = psi4[t];

    // ---- K0 (one thread per token) ----
    if (c == 0) out[t] = dot4f(p, p);

    // ---- u_c = gamma_c^T p ; v_c = gamma_c p ----
    const float4 r0 = sg[c * 4 + 0];
    const float4 r1 = sg[c * 4 + 1];
    const float4 r2 = sg[c * 4 + 2];
    const float4 r3 = sg[c * 4 + 3];

    float4 v;   // gamma_c @ p
    v.x = fmaf(r0.x, p.x, fmaf(r0.y, p.y, fmaf(r0.z, p.z, r0.w * p.w)));
    v.y = fmaf(r1.x, p.x, fmaf(r1.y, p.y, fmaf(r1.z, p.z, r1.w * p.w)));
    v.z = fmaf(r2.x, p.x, fmaf(r2.y, p.y, fmaf(r2.z, p.z, r2.w * p.w)));
    v.w = fmaf(r3.x, p.x, fmaf(r3.y, p.y, fmaf(r3.z, p.z, r3.w * p.w)));

    float4 u;   // gamma_c^T @ p
    u.x = fmaf(r0.x, p.x, fmaf(r1.x, p.y, fmaf(r2.x, p.z, r3.x * p.w)));
    u.y = fmaf(r0.y, p.x, fmaf(r1.y, p.y, fmaf(r2.y, p.z, r3.y * p.w)));
    u.z = fmaf(r0.z, p.x, fmaf(r1.z, p.y, fmaf(r2.z, p.z, r3.z * p.w)));
    u.w = fmaf(r0.w, p.x, fmaf(r1.w, p.y, fmaf(r2.w, p.z, r3.w * p.w)));

    su[tokL * 9 + c] = u;
    sv[tokL * 9 + c] = v;
    __syncthreads();

    // ---- row c of K1/K2: needs u_d, v_d for d=0..7 (broadcast smem reads) ----
    float k1[8], k2[8];
#pragma unroll
    for (int d = 0; d < 8; d++) {
        const float4 ud = su[tokL * 9 + d];
        const float4 vd = sv[tokL * 9 + d];
        const float w  = dot4f(u, vd);     // W[c][d]
        const float wt = dot4f(ud, v);     // W[d][c]
        k1[d] = 0.5f * (w - wt);
        k2[d] = 0.5f * (w + wt);
    }

    // ---- direct coalesced stores: thread owns 32 B at t*64 + c*8 ----
    const size_t bn   = (size_t)BN;
    const size_t base = (size_t)t * 64 + (size_t)c * 8;

    float4* __restrict__ o1 = reinterpret_cast<float4*>(out + bn + base);
    o1[0] = make_float4(k1[0], k1[1], k1[2], k1[3]);
    o1[1] = make_float4(k1[4], k1[5], k1[6], k1[7]);

    float4* __restrict__ o2 = reinterpret_cast<float4*>(out + bn + bn * 64 + base);
    o2[0] = make_float4(k2[0], k2[1], k2[2], k2[3]);
    o2[1] = make_float4(k2[4], k2[5], k2[6], k2[7]);
}

extern "C" void kernel_launch(void* const* d_in, const int* in_sizes, int n_in,
                              void* d_out, int out_size) {
    const float4* psi4   = (const float4*)d_in[0];   // [B, N, 4] f32
    const float4* gamma4 = (const float4*)d_in[1];   // [8, 4, 4] f32
    float* out = (float*)d_out;

    const int BN   = in_sizes[0] / 4;    // 524288 tokens
    const int grid = BN / TOKS;          // 16384 blocks, exact

    spinor_bilinears_kernel<<<grid, TPB>>>(psi4, gamma4, out, BN);
}

// round 5
// speedup vs baseline: 1.0205x; 1.0205x over previous
#include <cuda_runtime.h>

// SpinorBilinears: psi [B=8, N=65536, S=4] f32, gamma [C=8, 4, 4] f32.
// Outputs flat: K0 [BN] | K1 [BN,8,8] | K2 [BN,8,8]
//
// Algebra: W[c][d] = p^T gamma_c gamma_d p = <Gsym_cd[10], outer10(p)>
//   K1 = 0.5(W - W^T), K2 = 0.5(W + W^T)   (0.5 folded into coeffs)
// Prep kernel packs Gsym (64 pairs x 10 coeffs, padded to 12) once.
// Main kernel: 8 threads/token; thread c computes row w[d]=0.5*W[c][d],
// obtains wt[d]=0.5*W[d][c] via in-register 8x8 butterfly transpose (SHFL),
// stores rows directly (coalesced). No smem exchange, no hot-path barriers.

#define TPB 256

__device__ float g_coef[768];   // [64 pairs][12], row index = d*8+c for pair (c,d)

__global__ void spinor_prep_kernel(const float* __restrict__ gamma) {
    const int tid = threadIdx.x;          // 0..63
    const int c = tid >> 3, d = tid & 7;
    const float* gc = gamma + c * 16;
    const float* gd = gamma + d * 16;

    float G[4][4];
#pragma unroll
    for (int i = 0; i < 4; i++)
#pragma unroll
        for (int j = 0; j < 4; j++) {
            float s = 0.f;
#pragma unroll
            for (int k = 0; k < 4; k++) s = fmaf(gc[i * 4 + k], gd[k * 4 + j], s);
            G[i][j] = s;
        }

    float cf[12];
    cf[0] = G[0][0];            cf[1] = G[0][1] + G[1][0];
    cf[2] = G[0][2] + G[2][0];  cf[3] = G[0][3] + G[3][0];
    cf[4] = G[1][1];            cf[5] = G[1][2] + G[2][1];
    cf[6] = G[1][3] + G[3][1];  cf[7] = G[2][2];
    cf[8] = G[2][3] + G[3][2];  cf[9] = G[3][3];
    cf[10] = 0.f; cf[11] = 0.f;

    float* dst = &g_coef[(d * 8 + c) * 12];
#pragma unroll
    for (int k = 0; k < 12; k++) dst[k] = 0.5f * cf[k];
}

__global__ __launch_bounds__(TPB) void spinor_main_kernel(
    const float4* __restrict__ psi4,
    float* __restrict__ out,
    int BN)
{
    __shared__ float sc[768];   // row stride 12 floats: 8 lanes' rows span all 32 banks

    const int tid = threadIdx.x;
    if (tid < 192)
        reinterpret_cast<float4*>(sc)[tid] =
            reinterpret_cast<const float4*>(g_coef)[tid];
    __syncthreads();

    const int gth = blockIdx.x * TPB + tid;
    const int t   = gth >> 3;           // token
    const int c   = tid & 7;            // row index 0..7

    const float4 p = psi4[t];           // 8 lanes/token share one 16B load (broadcast)

    float o[10];
    o[0] = p.x * p.x; o[1] = p.x * p.y; o[2] = p.x * p.z; o[3] = p.x * p.w;
    o[4] = p.y * p.y; o[5] = p.y * p.z; o[6] = p.y * p.w;
    o[7] = p.z * p.z; o[8] = p.z * p.w; o[9] = p.w * p.w;

    if (c == 0) out[t] = o[0] + o[4] + o[7] + o[9];   // K0

    // w[d] = 0.5 * W[c][d]
    float w[8];
#pragma unroll
    for (int d = 0; d < 8; d++) {
        const float4* cf4 = reinterpret_cast<const float4*>(&sc[(d * 8 + c) * 12]);
        const float4 a = cf4[0], b = cf4[1], e = cf4[2];
        float acc;
        acc = a.x * o[0];
        acc = fmaf(a.y, o[1], acc); acc = fmaf(a.z, o[2], acc);
        acc = fmaf(a.w, o[3], acc); acc = fmaf(b.x, o[4], acc);
        acc = fmaf(b.y, o[5], acc); acc = fmaf(b.z, o[6], acc);
        acc = fmaf(b.w, o[7], acc); acc = fmaf(e.x, o[8], acc);
        acc = fmaf(e.y, o[9], acc);
        w[d] = acc;
    }

    // wt[d] = 0.5 * W[d][c] via 8x8 in-register butterfly transpose (8-lane groups)
    float wt[8];
#pragma unroll
    for (int r = 0; r < 8; r++) wt[r] = w[r];
#pragma unroll
    for (int m = 1; m < 8; m <<= 1) {
        float nt[8];
#pragma unroll
        for (int r = 0; r < 8; r++) {
            const float other = __shfl_xor_sync(0xFFFFFFFFu, wt[r ^ m], m);
            nt[r] = ((c ^ r) & m) ? other : wt[r];
        }
#pragma unroll
        for (int r = 0; r < 8; r++) wt[r] = nt[r];
    }

    // direct coalesced stores: thread owns 32 B at t*64 + c*8 per tensor
    const size_t bn   = (size_t)BN;
    const size_t base = (size_t)t * 64 + (size_t)c * 8;

    float4* __restrict__ o1 = reinterpret_cast<float4*>(out + bn + base);
    o1[0] = make_float4(w[0] - wt[0], w[1] - wt[1], w[2] - wt[2], w[3] - wt[3]);
    o1[1] = make_float4(w[4] - wt[4], w[5] - wt[5], w[6] - wt[6], w[7] - wt[7]);

    float4* __restrict__ o2 = reinterpret_cast<float4*>(out + bn + bn * 64 + base);
    o2[0] = make_float4(w[0] + wt[0], w[1] + wt[1], w[2] + wt[2], w[3] + wt[3]);
    o2[1] = make_float4(w[4] + wt[4], w[5] + wt[5], w[6] + wt[6], w[7] + wt[7]);
}

extern "C" void kernel_launch(void* const* d_in, const int* in_sizes, int n_in,
                              void* d_out, int out_size) {
    const float4* psi4  = (const float4*)d_in[0];   // [B, N, 4] f32
    const float*  gamma = (const float*)d_in[1];    // [8, 4, 4] f32
    float* out = (float*)d_out;

    const int BN = in_sizes[0] / 4;                 // 524288 tokens

    spinor_prep_kernel<<<1, 64>>>(gamma);
    spinor_main_kernel<<<(BN * 8) / TPB, TPB>>>(psi4, out, BN);
}

// round 6
// speedup vs baseline: 1.0235x; 1.0029x over previous
#include <cuda_runtime.h>

// SpinorBilinears: psi [B=8, N=65536, S=4] f32, gamma [C=8, 4, 4] f32.
// Outputs flat: K0 [BN] | K1 [BN,8,8] | K2 [BN,8,8]
//
// Algebra: W[c][d] = p^T gamma_c gamma_d p = <Gsym_cd[10], outer10(p)>
//   K1 = 0.5(W - W^T), K2 = 0.5(W + W^T)   (0.5 folded into coeffs)
// Prep kernel packs Gsym (64 pairs x 10 coeffs, padded to 12) once.
// Main kernel: 8 threads/token; thread c computes row w[d]=0.5*W[c][d],
// obtains wt[d]=0.5*W[d][c] via in-register 8x8 butterfly transpose (SHFL),
// stores rows directly (coalesced). No smem exchange, no hot-path barriers.

#define TPB 256

__device__ float g_coef[768];   // [64 pairs][12], row index = d*8+c for pair (c,d)

__global__ void spinor_prep_kernel(const float* __restrict__ gamma) {
    const int tid = threadIdx.x;          // 0..63
    const int c = tid >> 3, d = tid & 7;
    const float* gc = gamma + c * 16;
    const float* gd = gamma + d * 16;

    float G[4][4];
#pragma unroll
    for (int i = 0; i < 4; i++)
#pragma unroll
        for (int j = 0; j < 4; j++) {
            float s = 0.f;
#pragma unroll
            for (int k = 0; k < 4; k++) s = fmaf(gc[i * 4 + k], gd[k * 4 + j], s);
            G[i][j] = s;
        }

    float cf[12];
    cf[0] = G[0][0];            cf[1] = G[0][1] + G[1][0];
    cf[2] = G[0][2] + G[2][0];  cf[3] = G[0][3] + G[3][0];
    cf[4] = G[1][1];            cf[5] = G[1][2] + G[2][1];
    cf[6] = G[1][3] + G[3][1];  cf[7] = G[2][2];
    cf[8] = G[2][3] + G[3][2];  cf[9] = G[3][3];
    cf[10] = 0.f; cf[11] = 0.f;

    float* dst = &g_coef[(d * 8 + c) * 12];
#pragma unroll
    for (int k = 0; k < 12; k++) dst[k] = 0.5f * cf[k];
}

__global__ __launch_bounds__(TPB) void spinor_main_kernel(
    const float4* __restrict__ psi4,
    float* __restrict__ out,
    int BN)
{
    __shared__ float sc[768];   // row stride 12 floats: 8 lanes' rows span all 32 banks

    const int tid = threadIdx.x;
    if (tid < 192)
        reinterpret_cast<float4*>(sc)[tid] =
            reinterpret_cast<const float4*>(g_coef)[tid];
    __syncthreads();

    const int gth = blockIdx.x * TPB + tid;
    const int t   = gth >> 3;           // token
    const int c   = tid & 7;            // row index 0..7

    const float4 p = psi4[t];           // 8 lanes/token share one 16B load (broadcast)

    float o[10];
    o[0] = p.x * p.x; o[1] = p.x * p.y; o[2] = p.x * p.z; o[3] = p.x * p.w;
    o[4] = p.y * p.y; o[5] = p.y * p.z; o[6] = p.y * p.w;
    o[7] = p.z * p.z; o[8] = p.z * p.w; o[9] = p.w * p.w;

    if (c == 0) out[t] = o[0] + o[4] + o[7] + o[9];   // K0

    // w[d] = 0.5 * W[c][d]
    float w[8];
#pragma unroll
    for (int d = 0; d < 8; d++) {
        const float4* cf4 = reinterpret_cast<const float4*>(&sc[(d * 8 + c) * 12]);
        const float4 a = cf4[0], b = cf4[1], e = cf4[2];
        float acc;
        acc = a.x * o[0];
        acc = fmaf(a.y, o[1], acc); acc = fmaf(a.z, o[2], acc);
        acc = fmaf(a.w, o[3], acc); acc = fmaf(b.x, o[4], acc);
        acc = fmaf(b.y, o[5], acc); acc = fmaf(b.z, o[6], acc);
        acc = fmaf(b.w, o[7], acc); acc = fmaf(e.x, o[8], acc);
        acc = fmaf(e.y, o[9], acc);
        w[d] = acc;
    }

    // wt[d] = 0.5 * W[d][c] via 8x8 in-register butterfly transpose (8-lane groups)
    float wt[8];
#pragma unroll
    for (int r = 0; r < 8; r++) wt[r] = w[r];
#pragma unroll
    for (int m = 1; m < 8; m <<= 1) {
        float nt[8];
#pragma unroll
        for (int r = 0; r < 8; r++) {
            const float other = __shfl_xor_sync(0xFFFFFFFFu, wt[r ^ m], m);
            nt[r] = ((c ^ r) & m) ? other : wt[r];
        }
#pragma unroll
        for (int r = 0; r < 8; r++) wt[r] = nt[r];
    }

    // direct coalesced stores: thread owns 32 B at t*64 + c*8 per tensor
    const size_t bn   = (size_t)BN;
    const size_t base = (size_t)t * 64 + (size_t)c * 8;

    float4* __restrict__ o1 = reinterpret_cast<float4*>(out + bn + base);
    o1[0] = make_float4(w[0] - wt[0], w[1] - wt[1], w[2] - wt[2], w[3] - wt[3]);
    o1[1] = make_float4(w[4] - wt[4], w[5] - wt[5], w[6] - wt[6], w[7] - wt[7]);

    float4* __restrict__ o2 = reinterpret_cast<float4*>(out + bn + bn * 64 + base);
    o2[0] = make_float4(w[0] + wt[0], w[1] + wt[1], w[2] + wt[2], w[3] + wt[3]);
    o2[1] = make_float4(w[4] + wt[4], w[5] + wt[5], w[6] + wt[6], w[7] + wt[7]);
}

extern "C" void kernel_launch(void* const* d_in, const int* in_sizes, int n_in,
                              void* d_out, int out_size) {
    const float4* psi4  = (const float4*)d_in[0];   // [B, N, 4] f32
    const float*  gamma = (const float*)d_in[1];    // [8, 4, 4] f32
    float* out = (float*)d_out;

    const int BN = in_sizes[0] / 4;                 // 524288 tokens

    spinor_prep_kernel<<<1, 64>>>(gamma);
    spinor_main_kernel<<<(BN * 8) / TPB, TPB>>>(psi4, out, BN);
}